// round 4
// baseline (speedup 1.0000x reference)
#include <cuda_runtime.h>
#include <math.h>

#define NTOK 8192
#define DM   1024
#define PROJ 256
#define RHID 256
#define EHID 256
#define NE   8
#define RAWF 512
#define RIN  1280

// output layout (floats), tuple order flattened
#define OFF_NEXT   0L
#define OFF_STAGE  8388608L
#define OFF_GATE   16777216L
#define OFF_SCALED 16842752L
#define OFF_GROUP  16908288L
#define OFF_RULE   16941056L

// scratch (device globals; no allocation allowed)
static __device__ __align__(16) float g_hnorm[NTOK * DM];
static __device__ __align__(16) float g_rin[NTOK * RIN];
static __device__ __align__(16) float g_h1[NTOK * PROJ];
static __device__ __align__(16) float g_rh1[NTOK * RHID];
static __device__ __align__(16) float g_logits[NTOK * NE];
static __device__ __align__(16) float g_Hbuf[(long)NE * NTOK * EHID];
static __device__ int g_cnt[NE];
static __device__ int g_idx[NE * NTOK];

__device__ __forceinline__ float gelu_f(float x) {
    // jax.nn.gelu approximate=True (tanh form)
    const float c = 0.7978845608028654f;
    float t = tanhf(c * (x + 0.044715f * x * x * x));
    return 0.5f * x * (1.0f + t);
}

__device__ __forceinline__ float warpsum(float v) {
    #pragma unroll
    for (int o = 16; o; o >>= 1) v += __shfl_xor_sync(0xFFFFFFFFu, v, o);
    return v;
}

// ---------------------------------------------------------------------------
// Kernel 1: layernorm -> g_hnorm and g_rin[:, :1024]; rule logits; zero
// stage_out region of d_out; zero g_cnt (block 0).
// ---------------------------------------------------------------------------
__global__ void __launch_bounds__(256) ln_kernel(
    const float* __restrict__ hidden,
    const float* __restrict__ ln_g, const float* __restrict__ ln_b,
    const float* __restrict__ feat,
    const float* __restrict__ rr_w, const float* __restrict__ rr_b,
    float* __restrict__ out)
{
    int t = blockIdx.x;
    int tid = threadIdx.x;
    long base = (long)t * DM + tid * 4;
    float4 x = *(const float4*)(hidden + base);

    float s1 = x.x + x.y + x.z + x.w;
    float s2 = x.x * x.x + x.y * x.y + x.z * x.z + x.w * x.w;

    __shared__ float sm1[8], sm2[8];
    float w1 = warpsum(s1), w2 = warpsum(s2);
    if ((tid & 31) == 0) { sm1[tid >> 5] = w1; sm2[tid >> 5] = w2; }
    __syncthreads();
    __shared__ float s_mu, s_inv;
    if (tid == 0) {
        float a = 0.f, c = 0.f;
        #pragma unroll
        for (int i = 0; i < 8; i++) { a += sm1[i]; c += sm2[i]; }
        float m = a * (1.0f / DM);
        float var = c * (1.0f / DM) - m * m;
        s_mu = m;
        s_inv = rsqrtf(var + 1e-5f);
    }
    __syncthreads();
    float mu = s_mu, inv = s_inv;

    float4 gg = *(const float4*)(ln_g + tid * 4);
    float4 bb = *(const float4*)(ln_b + tid * 4);
    float4 y;
    y.x = (x.x - mu) * inv * gg.x + bb.x;
    y.y = (x.y - mu) * inv * gg.y + bb.y;
    y.z = (x.z - mu) * inv * gg.z + bb.z;
    y.w = (x.w - mu) * inv * gg.w + bb.w;

    *(float4*)(g_hnorm + base) = y;
    *(float4*)(g_rin + (long)t * RIN + tid * 4) = y;

    // zero stage_out accumulator region
    float4 z4 = make_float4(0.f, 0.f, 0.f, 0.f);
    *(float4*)(out + OFF_STAGE + base) = z4;

    // rule target logits (TEMP = 1)
    if (tid < NE) {
        float acc = rr_b[tid];
        #pragma unroll
        for (int k = 0; k < 16; k++) acc += feat[t * 16 + k] * rr_w[k * NE + tid];
        out[OFF_RULE + (long)t * NE + tid] = acc;
    }
    if (t == 0 && tid < NE) g_cnt[tid] = 0;
}

// ---------------------------------------------------------------------------
// Generic tiled fp32 GEMM: C[z] = act(A @ B[z] + bias[z])
// BM=BN=64, BK=16, 256 threads, 4x4 microtile. Optional row gather via idx
// list and runtime M via cnt (for expert GEMM1).
// ---------------------------------------------------------------------------
#define BM 64
#define BN 64
#define BK 16

__global__ void __launch_bounds__(256) gemm_kernel(
    const float* __restrict__ A,
    const float* __restrict__ Bw,
    const float* __restrict__ bias,
    float* __restrict__ C,
    int N, int K, int lda, int ldc,
    long bStride, long cStride, int biasStride,
    const int* __restrict__ gIdx,
    const int* __restrict__ cntArr,
    int Mfixed, int do_gelu)
{
    int z = blockIdx.z;
    int M = cntArr ? cntArr[z] : Mfixed;
    int m0 = blockIdx.y * BM;
    if (m0 >= M) return;
    const float* B = Bw + (long)z * bStride;
    float* Cz = C + (long)z * cStride;
    const float* bz = bias + (long)z * biasStride;
    const int* idx = gIdx ? (gIdx + z * NTOK) : (const int*)0;
    int n0 = blockIdx.x * BN;

    __shared__ float As[BK][BM];
    __shared__ float Bs[BK][BN];

    int tid = threadIdx.x;
    int ar = tid >> 2, ac = (tid & 3) << 2;    // A tile load: row, col4
    int br = tid >> 4, bc = (tid & 15) << 2;   // B tile load
    int ty = tid >> 4, tx = tid & 15;          // compute microtile

    float acc[16];
    #pragma unroll
    for (int i = 0; i < 16; i++) acc[i] = 0.f;

    int arow = m0 + ar;
    bool av = arow < M;
    long aoff = 0;
    if (av) {
        int g = idx ? idx[arow] : arow;
        aoff = (long)g * lda;
    }
    const float* bp = B + (long)br * N + n0 + bc;

    for (int k0 = 0; k0 < K; k0 += BK) {
        float4 a4 = av ? *(const float4*)(A + aoff + k0 + ac)
                       : make_float4(0.f, 0.f, 0.f, 0.f);
        As[ac + 0][ar] = a4.x; As[ac + 1][ar] = a4.y;
        As[ac + 2][ar] = a4.z; As[ac + 3][ar] = a4.w;
        *(float4*)&Bs[br][bc] = *(const float4*)(bp + (long)k0 * N);
        __syncthreads();
        #pragma unroll
        for (int k = 0; k < BK; k++) {
            float4 a = *(const float4*)&As[k][ty << 2];
            float4 b = *(const float4*)&Bs[k][tx << 2];
            acc[0]  += a.x * b.x; acc[1]  += a.x * b.y; acc[2]  += a.x * b.z; acc[3]  += a.x * b.w;
            acc[4]  += a.y * b.x; acc[5]  += a.y * b.y; acc[6]  += a.y * b.z; acc[7]  += a.y * b.w;
            acc[8]  += a.z * b.x; acc[9]  += a.z * b.y; acc[10] += a.z * b.z; acc[11] += a.z * b.w;
            acc[12] += a.w * b.x; acc[13] += a.w * b.y; acc[14] += a.w * b.z; acc[15] += a.w * b.w;
        }
        __syncthreads();
    }

    float4 bb = *(const float4*)(bz + n0 + (tx << 2));
    #pragma unroll
    for (int r = 0; r < 4; r++) {
        int gr = m0 + (ty << 2) + r;
        if (gr < M) {
            float4 v;
            v.x = acc[r * 4 + 0] + bb.x;
            v.y = acc[r * 4 + 1] + bb.y;
            v.z = acc[r * 4 + 2] + bb.z;
            v.w = acc[r * 4 + 3] + bb.w;
            if (do_gelu) {
                v.x = gelu_f(v.x); v.y = gelu_f(v.y);
                v.z = gelu_f(v.z); v.w = gelu_f(v.w);
            }
            *(float4*)(Cz + (long)gr * ldc + n0 + (tx << 2)) = v;
        }
    }
}

// ---------------------------------------------------------------------------
// Router logits: g_logits = g_rh1 @ r_w2 + r_b2   (N=8)
// ---------------------------------------------------------------------------
__global__ void __launch_bounds__(256) logits_kernel(
    const float* __restrict__ r_w2, const float* __restrict__ r_b2)
{
    __shared__ float sh[32 * 257];
    __shared__ float w2s[RHID * NE];
    int tid = threadIdx.x;
    int t0 = blockIdx.x * 32;
    for (int i = tid; i < 32 * RHID; i += 256) {
        int r = i >> 8, c = i & 255;
        sh[r * 257 + c] = g_rh1[(long)(t0 + r) * RHID + c];
    }
    for (int i = tid; i < RHID * NE; i += 256) w2s[i] = r_w2[i];
    __syncthreads();
    int j = tid >> 3, e = tid & 7;
    float acc = r_b2[e];
    #pragma unroll 8
    for (int k = 0; k < RHID; k++) acc += sh[j * 257 + k] * w2s[k * NE + e];
    g_logits[(long)(t0 + j) * NE + e] = acc;
}

// ---------------------------------------------------------------------------
// Gate: exact top-2-with-ties softmax, write gate/scaled/group outputs,
// build per-expert token lists.
// ---------------------------------------------------------------------------
__global__ void __launch_bounds__(256) gate_kernel(float* __restrict__ out)
{
    int t = blockIdx.x * blockDim.x + threadIdx.x;
    if (t >= NTOK) return;
    float l[8];
    #pragma unroll
    for (int e = 0; e < NE; e++) l[e] = g_logits[(long)t * NE + e];

    float m1 = -INFINITY, m2 = -INFINITY;
    #pragma unroll
    for (int e = 0; e < NE; e++) {
        float v = l[e];
        if (v > m1) { m2 = m1; m1 = v; }
        else if (v > m2) { m2 = v; }
    }
    float thresh = m2;

    float w[8];
    float sum = 0.f;
    #pragma unroll
    for (int e = 0; e < NE; e++) {
        if (l[e] >= thresh) { w[e] = expf(l[e] - m1); sum += w[e]; }
        else w[e] = 0.f;
    }
    float rinv = 1.0f / sum;
    #pragma unroll
    for (int e = 0; e < NE; e++) {
        float ww = w[e] * rinv;
        out[OFF_GATE + (long)t * NE + e] = ww;
        out[OFF_SCALED + (long)t * NE + e] = l[e];  // TEMP = 1
        if (l[e] >= thresh) {
            int s = atomicAdd(&g_cnt[e], 1);
            g_idx[e * NTOK + s] = t;
        }
        w[e] = ww;
    }
    #pragma unroll
    for (int g = 0; g < NE / 2; g++)
        out[OFF_GROUP + (long)t * (NE / 2) + g] = w[2 * g] + w[2 * g + 1];
}

// ---------------------------------------------------------------------------
// Expert GEMM2 + weighted scatter: stage_out[tok] += w * (H @ e_w2[z] + b2[z])
// A = g_Hbuf[z] (rows = slots), K=256, N=1024.
// ---------------------------------------------------------------------------
__global__ void __launch_bounds__(256) expert2_kernel(
    const float* __restrict__ e_w2,
    const float* __restrict__ e_b2,
    float* __restrict__ out)
{
    int z = blockIdx.z;
    int M = g_cnt[z];
    int m0 = blockIdx.y * BM;
    if (m0 >= M) return;
    const float* A = g_Hbuf + (long)z * NTOK * EHID;
    const float* B = e_w2 + (long)z * EHID * DM;
    const float* bz = e_b2 + z * DM;
    const int* idx = g_idx + z * NTOK;
    int n0 = blockIdx.x * BN;

    __shared__ float As[BK][BM];
    __shared__ float Bs[BK][BN];

    int tid = threadIdx.x;
    int ar = tid >> 2, ac = (tid & 3) << 2;
    int br = tid >> 4, bc = (tid & 15) << 2;
    int ty = tid >> 4, tx = tid & 15;

    float acc[16];
    #pragma unroll
    for (int i = 0; i < 16; i++) acc[i] = 0.f;

    int arow = m0 + ar;
    bool av = arow < M;
    long aoff = (long)arow * EHID;
    const float* bp = B + (long)br * DM + n0 + bc;

    for (int k0 = 0; k0 < EHID; k0 += BK) {
        float4 a4 = av ? *(const float4*)(A + aoff + k0 + ac)
                       : make_float4(0.f, 0.f, 0.f, 0.f);
        As[ac + 0][ar] = a4.x; As[ac + 1][ar] = a4.y;
        As[ac + 2][ar] = a4.z; As[ac + 3][ar] = a4.w;
        *(float4*)&Bs[br][bc] = *(const float4*)(bp + (long)k0 * DM);
        __syncthreads();
        #pragma unroll
        for (int k = 0; k < BK; k++) {
            float4 a = *(const float4*)&As[k][ty << 2];
            float4 b = *(const float4*)&Bs[k][tx << 2];
            acc[0]  += a.x * b.x; acc[1]  += a.x * b.y; acc[2]  += a.x * b.z; acc[3]  += a.x * b.w;
            acc[4]  += a.y * b.x; acc[5]  += a.y * b.y; acc[6]  += a.y * b.z; acc[7]  += a.y * b.w;
            acc[8]  += a.z * b.x; acc[9]  += a.z * b.y; acc[10] += a.z * b.z; acc[11] += a.z * b.w;
            acc[12] += a.w * b.x; acc[13] += a.w * b.y; acc[14] += a.w * b.z; acc[15] += a.w * b.w;
        }
        __syncthreads();
    }

    float4 bb = *(const float4*)(bz + n0 + (tx << 2));
    #pragma unroll
    for (int r = 0; r < 4; r++) {
        int gr = m0 + (ty << 2) + r;
        if (gr < M) {
            int tok = idx[gr];
            float w = out[OFF_GATE + (long)tok * NE + z];
            float* dst = out + OFF_STAGE + (long)tok * DM + n0 + (tx << 2);
            atomicAdd(dst + 0, w * (acc[r * 4 + 0] + bb.x));
            atomicAdd(dst + 1, w * (acc[r * 4 + 1] + bb.y));
            atomicAdd(dst + 2, w * (acc[r * 4 + 2] + bb.z));
            atomicAdd(dst + 3, w * (acc[r * 4 + 3] + bb.w));
        }
    }
}

// ---------------------------------------------------------------------------
// Final: next_hidden = hidden + alpha * stage_out
// ---------------------------------------------------------------------------
__global__ void __launch_bounds__(256) final_kernel(
    const float* __restrict__ hidden,
    const float* __restrict__ alpha,
    float* __restrict__ out)
{
    long i = ((long)blockIdx.x * 256 + threadIdx.x) * 4;
    float a = *alpha;
    float4 h = *(const float4*)(hidden + i);
    float4 s = *(const float4*)(out + OFF_STAGE + i);
    float4 n;
    n.x = h.x + a * s.x; n.y = h.y + a * s.y;
    n.z = h.z + a * s.z; n.w = h.w + a * s.w;
    *(float4*)(out + OFF_NEXT + i) = n;
}

// ---------------------------------------------------------------------------
extern "C" void kernel_launch(void* const* d_in, const int* in_sizes, int n_in,
                              void* d_out, int out_size)
{
    const float* hidden = (const float*)d_in[0];
    const float* feat   = (const float*)d_in[1];
    const float* bank   = (const float*)d_in[2];   // (B,S,16,32) == (tok,512)
    // d_in[3] item_seq_len: unused by reference
    const float* ln_g  = (const float*)d_in[4];
    const float* ln_b  = (const float*)d_in[5];
    const float* fp_w1 = (const float*)d_in[6];
    const float* fp_b1 = (const float*)d_in[7];
    const float* fp_w2 = (const float*)d_in[8];
    const float* fp_b2 = (const float*)d_in[9];
    const float* r_w1  = (const float*)d_in[10];
    const float* r_b1  = (const float*)d_in[11];
    const float* r_w2  = (const float*)d_in[12];
    const float* r_b2  = (const float*)d_in[13];
    const float* rr_w  = (const float*)d_in[14];
    const float* rr_b  = (const float*)d_in[15];
    const float* e_w1  = (const float*)d_in[16];
    const float* e_b1  = (const float*)d_in[17];
    const float* e_w2  = (const float*)d_in[18];
    const float* e_b2  = (const float*)d_in[19];
    const float* alpha = (const float*)d_in[20];
    float* out = (float*)d_out;

    float *p_hnorm, *p_rin, *p_h1, *p_rh1, *p_Hbuf;
    int *p_cnt, *p_idx;
    cudaGetSymbolAddress((void**)&p_hnorm, g_hnorm);
    cudaGetSymbolAddress((void**)&p_rin,   g_rin);
    cudaGetSymbolAddress((void**)&p_h1,    g_h1);
    cudaGetSymbolAddress((void**)&p_rh1,   g_rh1);
    cudaGetSymbolAddress((void**)&p_Hbuf,  g_Hbuf);
    cudaGetSymbolAddress((void**)&p_cnt,   g_cnt);
    cudaGetSymbolAddress((void**)&p_idx,   g_idx);

    // 1. layernorm (+ rule logits, zero stage_out & counters)
    ln_kernel<<<NTOK, 256>>>(hidden, ln_g, ln_b, feat, rr_w, rr_b, out);

    // 2. feat proj layer 1: gelu(bank @ fp_w1 + b1) -> g_h1
    gemm_kernel<<<dim3(PROJ / BN, NTOK / BM, 1), 256>>>(
        bank, fp_w1, fp_b1, p_h1,
        PROJ, RAWF, RAWF, PROJ, 0, 0, 0, nullptr, nullptr, NTOK, 1);

    // 3. feat proj layer 2: g_h1 @ fp_w2 + b2 -> g_rin[:, 1024:1280]
    gemm_kernel<<<dim3(PROJ / BN, NTOK / BM, 1), 256>>>(
        p_h1, fp_w2, fp_b2, p_rin + DM,
        PROJ, PROJ, PROJ, RIN, 0, 0, 0, nullptr, nullptr, NTOK, 0);

    // 4. router layer 1: gelu(g_rin @ r_w1 + b1) -> g_rh1
    gemm_kernel<<<dim3(RHID / BN, NTOK / BM, 1), 256>>>(
        p_rin, r_w1, r_b1, p_rh1,
        RHID, RIN, RIN, RHID, 0, 0, 0, nullptr, nullptr, NTOK, 1);

    // 5. router layer 2 (N=8) -> g_logits
    logits_kernel<<<NTOK / 32, 256>>>(r_w2, r_b2);

    // 6. gate: top-2 softmax + outputs + expert token lists
    gate_kernel<<<NTOK / 256, 256>>>(out);

    // 7. expert GEMM1 (gathered): gelu(h_norm[idx] @ e_w1[z] + b1[z]) -> g_Hbuf[z]
    gemm_kernel<<<dim3(EHID / BN, NTOK / BM, NE), 256>>>(
        p_hnorm, e_w1, e_b1, p_Hbuf,
        EHID, DM, DM, EHID,
        (long)DM * EHID, (long)NTOK * EHID, EHID,
        p_idx, p_cnt, 0, 1);

    // 8. expert GEMM2 + weighted scatter into stage_out
    expert2_kernel<<<dim3(DM / BN, NTOK / BM, NE), 256>>>(e_w2, e_b2, out);

    // 9. next_hidden = hidden + alpha * stage_out
    final_kernel<<<NTOK, 256>>>(hidden, alpha, out);
}

// round 6
// speedup vs baseline: 1.2103x; 1.2103x over previous
#include <cuda_runtime.h>
#include <math.h>

#define NTOK 8192
#define DM   1024
#define PROJ 256
#define RHID 256
#define EHID 256
#define NE   8
#define RAWF 512
#define RIN  1280

// output layout (floats), tuple order flattened
#define OFF_NEXT   0L
#define OFF_STAGE  8388608L
#define OFF_GATE   16777216L
#define OFF_SCALED 16842752L
#define OFF_GROUP  16908288L
#define OFF_RULE   16941056L

// scratch (device globals; no allocation allowed)
static __device__ __align__(16) float g_hnorm[NTOK * DM];
static __device__ __align__(16) float g_rin[NTOK * RIN];
static __device__ __align__(16) float g_h1[NTOK * PROJ];
static __device__ __align__(16) float g_rh1[NTOK * RHID];
static __device__ __align__(16) float g_logits[NTOK * NE];
static __device__ __align__(16) float g_Hbuf[(long)NE * NTOK * EHID];
static __device__ int g_cnt[NE];
static __device__ int g_idx[NE * NTOK];

__device__ __forceinline__ float gelu_f(float x) {
    const float c = 0.7978845608028654f;
    float t = tanhf(c * (x + 0.044715f * x * x * x));
    return 0.5f * x * (1.0f + t);
}

__device__ __forceinline__ float warpsum(float v) {
    #pragma unroll
    for (int o = 16; o; o >>= 1) v += __shfl_xor_sync(0xFFFFFFFFu, v, o);
    return v;
}

__device__ __forceinline__ float cvt_tf32(float x) {
    unsigned u;
    asm("cvt.rna.tf32.f32 %0, %1;" : "=r"(u) : "f"(x));
    return __uint_as_float(u);
}

__device__ __forceinline__ void mma8(float* c, const unsigned* a, const unsigned* b) {
    asm volatile(
        "mma.sync.aligned.m16n8k8.row.col.f32.tf32.tf32.f32 "
        "{%0,%1,%2,%3}, {%4,%5,%6,%7}, {%8,%9}, {%0,%1,%2,%3};"
        : "+f"(c[0]), "+f"(c[1]), "+f"(c[2]), "+f"(c[3])
        : "r"(a[0]), "r"(a[1]), "r"(a[2]), "r"(a[3]),
          "r"(b[0]), "r"(b[1]));
}

// ---------------------------------------------------------------------------
// Kernel 1: layernorm -> g_hnorm and g_rin[:, :1024]; rule logits; zero
// stage_out region of d_out; zero g_cnt (block 0).
// ---------------------------------------------------------------------------
__global__ void __launch_bounds__(256) ln_kernel(
    const float* __restrict__ hidden,
    const float* __restrict__ ln_g, const float* __restrict__ ln_b,
    const float* __restrict__ feat,
    const float* __restrict__ rr_w, const float* __restrict__ rr_b,
    float* __restrict__ out)
{
    int t = blockIdx.x;
    int tid = threadIdx.x;
    long base = (long)t * DM + tid * 4;
    float4 x = *(const float4*)(hidden + base);

    float s1 = x.x + x.y + x.z + x.w;
    float s2 = x.x * x.x + x.y * x.y + x.z * x.z + x.w * x.w;

    __shared__ float sm1[8], sm2[8];
    float w1 = warpsum(s1), w2 = warpsum(s2);
    if ((tid & 31) == 0) { sm1[tid >> 5] = w1; sm2[tid >> 5] = w2; }
    __syncthreads();
    __shared__ float s_mu, s_inv;
    if (tid == 0) {
        float a = 0.f, c = 0.f;
        #pragma unroll
        for (int i = 0; i < 8; i++) { a += sm1[i]; c += sm2[i]; }
        float m = a * (1.0f / DM);
        float var = c * (1.0f / DM) - m * m;
        s_mu = m;
        s_inv = rsqrtf(var + 1e-5f);
    }
    __syncthreads();
    float mu = s_mu, inv = s_inv;

    float4 gg = *(const float4*)(ln_g + tid * 4);
    float4 bb = *(const float4*)(ln_b + tid * 4);
    float4 y;
    y.x = (x.x - mu) * inv * gg.x + bb.x;
    y.y = (x.y - mu) * inv * gg.y + bb.y;
    y.z = (x.z - mu) * inv * gg.z + bb.z;
    y.w = (x.w - mu) * inv * gg.w + bb.w;

    *(float4*)(g_hnorm + base) = y;
    *(float4*)(g_rin + (long)t * RIN + tid * 4) = y;

    float4 z4 = make_float4(0.f, 0.f, 0.f, 0.f);
    *(float4*)(out + OFF_STAGE + base) = z4;

    if (tid < NE) {
        float acc = rr_b[tid];
        #pragma unroll
        for (int k = 0; k < 16; k++) acc += feat[t * 16 + k] * rr_w[k * NE + tid];
        out[OFF_RULE + (long)t * NE + tid] = acc;
    }
    if (t == 0 && tid < NE) g_cnt[tid] = 0;
}

// ---------------------------------------------------------------------------
// 3xtf32 tensor-core GEMM: C[z] = epi(A[z] @ B[z] + bias[z]) at ~fp32 accuracy.
// x = x_hi + x_lo (tf32 split); x*y ~= xh*yh + xh*yl + xl*yh, fp32 accumulate.
// CTA tile 128x128x16, 256 threads = 8 warps (2x4), warp tile 64x32.
// mode: 0 = store, 1 = gelu+store, 2 = weighted atomic scatter to stage_out.
// gatherA: A rows indirected through idx (expert GEMM1).
// ---------------------------------------------------------------------------
#define TBM 128
#define TBN 128
#define TBK 16
#define APAD 20
#define BPAD 136

__global__ void __launch_bounds__(256) mma_gemm(
    const float* __restrict__ A,
    const float* __restrict__ Bw,
    const float* __restrict__ bias,
    float* __restrict__ C,
    int N, int K, int lda, int ldc,
    long aStride, long bStride, long cStride, int biasStride,
    const int* __restrict__ gIdx,
    const int* __restrict__ cntArr,
    int Mfixed, int mode, int gatherA,
    float* __restrict__ outbase)
{
    int z = blockIdx.z;
    int M = cntArr ? cntArr[z] : Mfixed;
    int m0 = blockIdx.y * TBM;
    if (m0 >= M) return;
    int n0 = blockIdx.x * TBN;
    const float* Az = A + (long)z * aStride;
    const float* B = Bw + (long)z * bStride;
    float* Cz = C + (long)z * cStride;
    const float* bz = bias + (long)z * biasStride;
    const int* idx = gIdx ? (gIdx + z * NTOK) : (const int*)0;

    __shared__ float As_hi[TBM][APAD];
    __shared__ float As_lo[TBM][APAD];
    __shared__ float Bs_hi[TBK][BPAD];
    __shared__ float Bs_lo[TBK][BPAD];

    int tid = threadIdx.x;

    // A staging: 2 float4/thread; id -> row = id>>2, col4 = id&3
    long aOff[2]; bool aV[2];
    #pragma unroll
    for (int j = 0; j < 2; j++) {
        int id = tid + 256 * j;
        int r = id >> 2, c4 = id & 3;
        int gm = m0 + r;
        aV[j] = gm < M;
        int gr = 0;
        if (aV[j]) gr = gatherA ? idx[gm] : gm;
        aOff[j] = (long)gr * lda + c4 * 4;
    }

    float4 ra[2], rb[2];
    #pragma unroll
    for (int j = 0; j < 2; j++)
        ra[j] = aV[j] ? *(const float4*)(Az + aOff[j]) : make_float4(0.f,0.f,0.f,0.f);
    #pragma unroll
    for (int j = 0; j < 2; j++) {
        int id = tid + 256 * j;
        int r = id >> 5, c4 = id & 31;
        rb[j] = *(const float4*)(B + (long)r * N + n0 + c4 * 4);
    }

    float acc[4][4][4];
    #pragma unroll
    for (int a = 0; a < 4; a++)
        #pragma unroll
        for (int b = 0; b < 4; b++)
            #pragma unroll
            for (int cc = 0; cc < 4; cc++) acc[a][b][cc] = 0.f;

    int wid = tid >> 5, lane = tid & 31;
    int wm = (wid >> 2) * 64, wn = (wid & 3) * 32;
    int g = lane >> 2, q = lane & 3;

    for (int k0 = 0; k0 < K; k0 += TBK) {
        // commit staged regs to smem as hi/lo tf32 splits
        #pragma unroll
        for (int j = 0; j < 2; j++) {
            int id = tid + 256 * j;
            int r = id >> 2, c = (id & 3) * 4;
            float v[4] = { ra[j].x, ra[j].y, ra[j].z, ra[j].w };
            #pragma unroll
            for (int i = 0; i < 4; i++) {
                float h = cvt_tf32(v[i]);
                As_hi[r][c + i] = h;
                As_lo[r][c + i] = cvt_tf32(v[i] - h);
            }
        }
        #pragma unroll
        for (int j = 0; j < 2; j++) {
            int id = tid + 256 * j;
            int r = id >> 5, c = (id & 31) * 4;
            float v[4] = { rb[j].x, rb[j].y, rb[j].z, rb[j].w };
            #pragma unroll
            for (int i = 0; i < 4; i++) {
                float h = cvt_tf32(v[i]);
                Bs_hi[r][c + i] = h;
                Bs_lo[r][c + i] = cvt_tf32(v[i] - h);
            }
        }
        __syncthreads();

        if (k0 + TBK < K) {
            #pragma unroll
            for (int j = 0; j < 2; j++)
                ra[j] = aV[j] ? *(const float4*)(Az + aOff[j] + k0 + TBK)
                              : make_float4(0.f,0.f,0.f,0.f);
            #pragma unroll
            for (int j = 0; j < 2; j++) {
                int id = tid + 256 * j;
                int r = id >> 5, c4 = id & 31;
                rb[j] = *(const float4*)(B + (long)(k0 + TBK + r) * N + n0 + c4 * 4);
            }
        }

        #pragma unroll
        for (int ks = 0; ks < 2; ks++) {
            int kk = ks * 8;
            unsigned ah[4][4], al[4][4], bh[4][2], bl[4][2];
            #pragma unroll
            for (int mt = 0; mt < 4; mt++) {
                int mr = wm + mt * 16 + g;
                ah[mt][0] = __float_as_uint(As_hi[mr][kk + q]);
                ah[mt][1] = __float_as_uint(As_hi[mr + 8][kk + q]);
                ah[mt][2] = __float_as_uint(As_hi[mr][kk + q + 4]);
                ah[mt][3] = __float_as_uint(As_hi[mr + 8][kk + q + 4]);
                al[mt][0] = __float_as_uint(As_lo[mr][kk + q]);
                al[mt][1] = __float_as_uint(As_lo[mr + 8][kk + q]);
                al[mt][2] = __float_as_uint(As_lo[mr][kk + q + 4]);
                al[mt][3] = __float_as_uint(As_lo[mr + 8][kk + q + 4]);
            }
            #pragma unroll
            for (int nt = 0; nt < 4; nt++) {
                int nc = wn + nt * 8 + g;
                bh[nt][0] = __float_as_uint(Bs_hi[kk + q][nc]);
                bh[nt][1] = __float_as_uint(Bs_hi[kk + q + 4][nc]);
                bl[nt][0] = __float_as_uint(Bs_lo[kk + q][nc]);
                bl[nt][1] = __float_as_uint(Bs_lo[kk + q + 4][nc]);
            }
            #pragma unroll
            for (int mt = 0; mt < 4; mt++)
                #pragma unroll
                for (int nt = 0; nt < 4; nt++) {
                    mma8(acc[mt][nt], al[mt], bh[nt]);
                    mma8(acc[mt][nt], ah[mt], bl[nt]);
                    mma8(acc[mt][nt], ah[mt], bh[nt]);
                }
        }
        __syncthreads();
    }

    // epilogue
    #pragma unroll
    for (int mt = 0; mt < 4; mt++) {
        int r0 = m0 + wm + mt * 16 + g;
        int r1 = r0 + 8;
        #pragma unroll
        for (int nt = 0; nt < 4; nt++) {
            int col = n0 + wn + nt * 8 + 2 * q;
            float b0 = bz[col], b1 = bz[col + 1];
            float v00 = acc[mt][nt][0] + b0, v01 = acc[mt][nt][1] + b1;
            float v10 = acc[mt][nt][2] + b0, v11 = acc[mt][nt][3] + b1;
            if (mode == 1) {
                v00 = gelu_f(v00); v01 = gelu_f(v01);
                v10 = gelu_f(v10); v11 = gelu_f(v11);
            }
            if (mode <= 1) {
                if (r0 < M) { float2 v = make_float2(v00, v01);
                              *(float2*)(Cz + (long)r0 * ldc + col) = v; }
                if (r1 < M) { float2 v = make_float2(v10, v11);
                              *(float2*)(Cz + (long)r1 * ldc + col) = v; }
            } else {
                if (r0 < M) {
                    int tok = idx[r0];
                    float w = outbase[OFF_GATE + (long)tok * NE + z];
                    float* dst = outbase + OFF_STAGE + (long)tok * DM + col;
                    atomicAdd(dst + 0, w * v00);
                    atomicAdd(dst + 1, w * v01);
                }
                if (r1 < M) {
                    int tok = idx[r1];
                    float w = outbase[OFF_GATE + (long)tok * NE + z];
                    float* dst = outbase + OFF_STAGE + (long)tok * DM + col;
                    atomicAdd(dst + 0, w * v10);
                    atomicAdd(dst + 1, w * v11);
                }
            }
        }
    }
}

// ---------------------------------------------------------------------------
// Router logits: g_logits = g_rh1 @ r_w2 + r_b2   (N=8, fp32)
// ---------------------------------------------------------------------------
__global__ void __launch_bounds__(256) logits_kernel(
    const float* __restrict__ r_w2, const float* __restrict__ r_b2)
{
    __shared__ float sh[32 * 257];
    __shared__ float w2s[RHID * NE];
    int tid = threadIdx.x;
    int t0 = blockIdx.x * 32;
    for (int i = tid; i < 32 * RHID; i += 256) {
        int r = i >> 8, c = i & 255;
        sh[r * 257 + c] = g_rh1[(long)(t0 + r) * RHID + c];
    }
    for (int i = tid; i < RHID * NE; i += 256) w2s[i] = r_w2[i];
    __syncthreads();
    int j = tid >> 3, e = tid & 7;
    float acc = r_b2[e];
    #pragma unroll 8
    for (int k = 0; k < RHID; k++) acc += sh[j * 257 + k] * w2s[k * NE + e];
    g_logits[(long)(t0 + j) * NE + e] = acc;
}

// ---------------------------------------------------------------------------
// Gate: exact top-2-with-ties softmax, write gate/scaled/group outputs,
// build per-expert token lists.
// ---------------------------------------------------------------------------
__global__ void __launch_bounds__(256) gate_kernel(float* __restrict__ out)
{
    int t = blockIdx.x * blockDim.x + threadIdx.x;
    if (t >= NTOK) return;
    float l[8];
    #pragma unroll
    for (int e = 0; e < NE; e++) l[e] = g_logits[(long)t * NE + e];

    float m1 = -INFINITY, m2 = -INFINITY;
    #pragma unroll
    for (int e = 0; e < NE; e++) {
        float v = l[e];
        if (v > m1) { m2 = m1; m1 = v; }
        else if (v > m2) { m2 = v; }
    }
    float thresh = m2;

    float w[8];
    float sum = 0.f;
    #pragma unroll
    for (int e = 0; e < NE; e++) {
        if (l[e] >= thresh) { w[e] = expf(l[e] - m1); sum += w[e]; }
        else w[e] = 0.f;
    }
    float rinv = 1.0f / sum;
    #pragma unroll
    for (int e = 0; e < NE; e++) {
        float ww = w[e] * rinv;
        out[OFF_GATE + (long)t * NE + e] = ww;
        out[OFF_SCALED + (long)t * NE + e] = l[e];
        if (l[e] >= thresh) {
            int s = atomicAdd(&g_cnt[e], 1);
            g_idx[e * NTOK + s] = t;
        }
        w[e] = ww;
    }
    #pragma unroll
    for (int g = 0; g < NE / 2; g++)
        out[OFF_GROUP + (long)t * (NE / 2) + g] = w[2 * g] + w[2 * g + 1];
}

// ---------------------------------------------------------------------------
// Final: next_hidden = hidden + alpha * stage_out
// ---------------------------------------------------------------------------
__global__ void __launch_bounds__(256) final_kernel(
    const float* __restrict__ hidden,
    const float* __restrict__ alpha,
    float* __restrict__ out)
{
    long i = ((long)blockIdx.x * 256 + threadIdx.x) * 4;
    float a = *alpha;
    float4 h = *(const float4*)(hidden + i);
    float4 s = *(const float4*)(out + OFF_STAGE + i);
    float4 n;
    n.x = h.x + a * s.x; n.y = h.y + a * s.y;
    n.z = h.z + a * s.z; n.w = h.w + a * s.w;
    *(float4*)(out + OFF_NEXT + i) = n;
}

// ---------------------------------------------------------------------------
extern "C" void kernel_launch(void* const* d_in, const int* in_sizes, int n_in,
                              void* d_out, int out_size)
{
    const float* hidden = (const float*)d_in[0];
    const float* feat   = (const float*)d_in[1];
    const float* bank   = (const float*)d_in[2];   // (tok, 512)
    const float* ln_g  = (const float*)d_in[4];
    const float* ln_b  = (const float*)d_in[5];
    const float* fp_w1 = (const float*)d_in[6];
    const float* fp_b1 = (const float*)d_in[7];
    const float* fp_w2 = (const float*)d_in[8];
    const float* fp_b2 = (const float*)d_in[9];
    const float* r_w1  = (const float*)d_in[10];
    const float* r_b1  = (const float*)d_in[11];
    const float* r_w2  = (const float*)d_in[12];
    const float* r_b2  = (const float*)d_in[13];
    const float* rr_w  = (const float*)d_in[14];
    const float* rr_b  = (const float*)d_in[15];
    const float* e_w1  = (const float*)d_in[16];
    const float* e_b1  = (const float*)d_in[17];
    const float* e_w2  = (const float*)d_in[18];
    const float* e_b2  = (const float*)d_in[19];
    const float* alpha = (const float*)d_in[20];
    float* out = (float*)d_out;

    float *p_hnorm, *p_rin, *p_h1, *p_rh1, *p_Hbuf;
    int *p_cnt, *p_idx;
    cudaGetSymbolAddress((void**)&p_hnorm, g_hnorm);
    cudaGetSymbolAddress((void**)&p_rin,   g_rin);
    cudaGetSymbolAddress((void**)&p_h1,    g_h1);
    cudaGetSymbolAddress((void**)&p_rh1,   g_rh1);
    cudaGetSymbolAddress((void**)&p_Hbuf,  g_Hbuf);
    cudaGetSymbolAddress((void**)&p_cnt,   g_cnt);
    cudaGetSymbolAddress((void**)&p_idx,   g_idx);

    // 1. layernorm (+ rule logits, zero stage_out & counters)
    ln_kernel<<<NTOK, 256>>>(hidden, ln_g, ln_b, feat, rr_w, rr_b, out);

    // 2. feat proj layer 1: gelu(bank @ fp_w1 + b1) -> g_h1
    mma_gemm<<<dim3(PROJ / TBN, NTOK / TBM, 1), 256>>>(
        bank, fp_w1, fp_b1, p_h1,
        PROJ, RAWF, RAWF, PROJ, 0, 0, 0, 0,
        nullptr, nullptr, NTOK, 1, 0, out);

    // 3. feat proj layer 2: g_h1 @ fp_w2 + b2 -> g_rin[:, 1024:1280]
    mma_gemm<<<dim3(PROJ / TBN, NTOK / TBM, 1), 256>>>(
        p_h1, fp_w2, fp_b2, p_rin + DM,
        PROJ, PROJ, PROJ, RIN, 0, 0, 0, 0,
        nullptr, nullptr, NTOK, 0, 0, out);

    // 4. router layer 1: gelu(g_rin @ r_w1 + b1) -> g_rh1
    mma_gemm<<<dim3(RHID / TBN, NTOK / TBM, 1), 256>>>(
        p_rin, r_w1, r_b1, p_rh1,
        RHID, RIN, RIN, RHID, 0, 0, 0, 0,
        nullptr, nullptr, NTOK, 1, 0, out);

    // 5. router layer 2 (N=8) -> g_logits
    logits_kernel<<<NTOK / 32, 256>>>(r_w2, r_b2);

    // 6. gate: top-2 softmax + outputs + expert token lists
    gate_kernel<<<NTOK / 256, 256>>>(out);

    // 7. expert GEMM1 (gathered): gelu(h_norm[idx] @ e_w1[z] + b1[z]) -> g_Hbuf[z]
    mma_gemm<<<dim3(EHID / TBN, NTOK / TBM, NE), 256>>>(
        p_hnorm, e_w1, e_b1, p_Hbuf,
        EHID, DM, DM, EHID,
        0, (long)DM * EHID, (long)NTOK * EHID, EHID,
        p_idx, p_cnt, 0, 1, 1, out);

    // 8. expert GEMM2 + weighted scatter into stage_out (A offset per expert!)
    mma_gemm<<<dim3(DM / TBN, NTOK / TBM, NE), 256>>>(
        p_Hbuf, e_w2, e_b2, out,
        DM, EHID, EHID, DM,
        (long)NTOK * EHID, (long)EHID * DM, 0, DM,
        p_idx, p_cnt, 0, 2, 0, out);

    // 9. next_hidden = hidden + alpha * stage_out
    final_kernel<<<NTOK, 256>>>(hidden, alpha, out);
}

// round 7
// speedup vs baseline: 1.6503x; 1.3636x over previous
#include <cuda_runtime.h>
#include <math.h>

#define NTOK 8192
#define DM   1024
#define PROJ 256
#define RHID 256
#define EHID 256
#define NE   8
#define RAWF 512
#define RIN  1280

// output layout (floats), tuple order flattened
#define OFF_NEXT   0L
#define OFF_STAGE  8388608L
#define OFF_GATE   16777216L
#define OFF_SCALED 16842752L
#define OFF_GROUP  16908288L
#define OFF_RULE   16941056L

// scratch (device globals; no allocation allowed)
static __device__ __align__(16) float g_hnorm[NTOK * DM];
static __device__ __align__(16) float g_rin[NTOK * RIN];
static __device__ __align__(16) float g_h1[NTOK * PROJ];
static __device__ __align__(16) float g_rh1[NTOK * RHID];
static __device__ __align__(16) float g_logits[NTOK * NE];
static __device__ __align__(16) float g_Hbuf[(long)NE * NTOK * EHID];
static __device__ int g_cnt[NE];
static __device__ int g_idx[NE * NTOK];

__device__ __forceinline__ float gelu_f(float x) {
    const float c = 0.7978845608028654f;
    float t = tanhf(c * (x + 0.044715f * x * x * x));
    return 0.5f * x * (1.0f + t);
}

__device__ __forceinline__ float warpsum(float v) {
    #pragma unroll
    for (int o = 16; o; o >>= 1) v += __shfl_xor_sync(0xFFFFFFFFu, v, o);
    return v;
}

__device__ __forceinline__ float cvt_tf32(float x) {
    unsigned u;
    asm("cvt.rna.tf32.f32 %0, %1;" : "=r"(u) : "f"(x));
    return __uint_as_float(u);
}

__device__ __forceinline__ void mma8(float* c, const unsigned* a, const unsigned* b) {
    asm volatile(
        "mma.sync.aligned.m16n8k8.row.col.f32.tf32.tf32.f32 "
        "{%0,%1,%2,%3}, {%4,%5,%6,%7}, {%8,%9}, {%0,%1,%2,%3};"
        : "+f"(c[0]), "+f"(c[1]), "+f"(c[2]), "+f"(c[3])
        : "r"(a[0]), "r"(a[1]), "r"(a[2]), "r"(a[3]),
          "r"(b[0]), "r"(b[1]));
}

// ---------------------------------------------------------------------------
// Kernel 1: layernorm -> g_hnorm and g_rin[:, :1024]; rule logits; zero
// stage_out region of d_out; zero g_cnt (block 0).
// ---------------------------------------------------------------------------
__global__ void __launch_bounds__(256) ln_kernel(
    const float* __restrict__ hidden,
    const float* __restrict__ ln_g, const float* __restrict__ ln_b,
    const float* __restrict__ feat,
    const float* __restrict__ rr_w, const float* __restrict__ rr_b,
    float* __restrict__ out)
{
    int t = blockIdx.x;
    int tid = threadIdx.x;
    long base = (long)t * DM + tid * 4;
    float4 x = *(const float4*)(hidden + base);

    float s1 = x.x + x.y + x.z + x.w;
    float s2 = x.x * x.x + x.y * x.y + x.z * x.z + x.w * x.w;

    __shared__ float sm1[8], sm2[8];
    float w1 = warpsum(s1), w2 = warpsum(s2);
    if ((tid & 31) == 0) { sm1[tid >> 5] = w1; sm2[tid >> 5] = w2; }
    __syncthreads();
    __shared__ float s_mu, s_inv;
    if (tid == 0) {
        float a = 0.f, c = 0.f;
        #pragma unroll
        for (int i = 0; i < 8; i++) { a += sm1[i]; c += sm2[i]; }
        float m = a * (1.0f / DM);
        float var = c * (1.0f / DM) - m * m;
        s_mu = m;
        s_inv = rsqrtf(var + 1e-5f);
    }
    __syncthreads();
    float mu = s_mu, inv = s_inv;

    float4 gg = *(const float4*)(ln_g + tid * 4);
    float4 bb = *(const float4*)(ln_b + tid * 4);
    float4 y;
    y.x = (x.x - mu) * inv * gg.x + bb.x;
    y.y = (x.y - mu) * inv * gg.y + bb.y;
    y.z = (x.z - mu) * inv * gg.z + bb.z;
    y.w = (x.w - mu) * inv * gg.w + bb.w;

    *(float4*)(g_hnorm + base) = y;
    *(float4*)(g_rin + (long)t * RIN + tid * 4) = y;

    float4 z4 = make_float4(0.f, 0.f, 0.f, 0.f);
    *(float4*)(out + OFF_STAGE + base) = z4;

    if (tid < NE) {
        float acc = rr_b[tid];
        #pragma unroll
        for (int k = 0; k < 16; k++) acc += feat[t * 16 + k] * rr_w[k * NE + tid];
        out[OFF_RULE + (long)t * NE + tid] = acc;
    }
    if (t == 0 && tid < NE) g_cnt[tid] = 0;
}

// ---------------------------------------------------------------------------
// tf32 tensor-core GEMM, templated precision:
//   PREC=3: 3xtf32 split (fp32-grade, for routing-critical GEMMs)
//   PREC=1: single-pass tf32 (~2e-4, for expert GEMMs after gating)
// Double-buffered SMEM, one __syncthreads per K-slab.
// CTA tile 128x128x16, 256 threads = 8 warps (2x4), warp tile 64x32.
// mode: 0 = store, 1 = gelu+store, 2 = weighted atomic scatter to stage_out.
// gatherA: A rows indirected through idx (expert GEMM1).
// ---------------------------------------------------------------------------
#define TBM 128
#define TBN 128
#define TBK 16
#define APAD 20
#define BPAD 136

template<int PREC>
__global__ void __launch_bounds__(256) mma_gemm(
    const float* __restrict__ A,
    const float* __restrict__ Bw,
    const float* __restrict__ bias,
    float* __restrict__ C,
    int N, int K, int lda, int ldc,
    long aStride, long bStride, long cStride, int biasStride,
    const int* __restrict__ gIdx,
    const int* __restrict__ cntArr,
    int Mfixed, int mode, int gatherA,
    float* __restrict__ outbase)
{
    int z = blockIdx.z;
    int M = cntArr ? cntArr[z] : Mfixed;
    int m0 = blockIdx.y * TBM;
    if (m0 >= M) return;
    int n0 = blockIdx.x * TBN;
    const float* Az = A + (long)z * aStride;
    const float* B = Bw + (long)z * bStride;
    float* Cz = C + (long)z * cStride;
    const float* bz = bias + (long)z * biasStride;
    const int* idx = gIdx ? (gIdx + z * NTOK) : (const int*)0;

    __shared__ float As_hi[2][TBM][APAD];
    __shared__ float Bs_hi[2][TBK][BPAD];
    __shared__ float As_lo[PREC == 3 ? 2 : 1][TBM][APAD];
    __shared__ float Bs_lo[PREC == 3 ? 2 : 1][TBK][BPAD];

    int tid = threadIdx.x;

    // A staging: 2 float4/thread; id -> row = id>>2, col4 = id&3
    long aOff[2]; bool aV[2];
    #pragma unroll
    for (int j = 0; j < 2; j++) {
        int id = tid + 256 * j;
        int r = id >> 2, c4 = id & 3;
        int gm = m0 + r;
        aV[j] = gm < M;
        int gr = 0;
        if (aV[j]) gr = gatherA ? idx[gm] : gm;
        aOff[j] = (long)gr * lda + c4 * 4;
    }

    float4 ra[2], rb[2];
    #pragma unroll
    for (int j = 0; j < 2; j++)
        ra[j] = aV[j] ? *(const float4*)(Az + aOff[j]) : make_float4(0.f,0.f,0.f,0.f);
    #pragma unroll
    for (int j = 0; j < 2; j++) {
        int id = tid + 256 * j;
        int r = id >> 5, c4 = id & 31;
        rb[j] = *(const float4*)(B + (long)r * N + n0 + c4 * 4);
    }

    float acc[4][4][4];
    #pragma unroll
    for (int a = 0; a < 4; a++)
        #pragma unroll
        for (int b = 0; b < 4; b++)
            #pragma unroll
            for (int cc = 0; cc < 4; cc++) acc[a][b][cc] = 0.f;

    int wid = tid >> 5, lane = tid & 31;
    int wm = (wid >> 2) * 64, wn = (wid & 3) * 32;
    int g = lane >> 2, q = lane & 3;

    int buf = 0;
    for (int k0 = 0; k0 < K; k0 += TBK) {
        // commit staged regs to smem[buf]
        #pragma unroll
        for (int j = 0; j < 2; j++) {
            int id = tid + 256 * j;
            int r = id >> 2, c = (id & 3) * 4;
            float v[4] = { ra[j].x, ra[j].y, ra[j].z, ra[j].w };
            #pragma unroll
            for (int i = 0; i < 4; i++) {
                float h = cvt_tf32(v[i]);
                As_hi[buf][r][c + i] = h;
                if (PREC == 3) As_lo[buf][r][c + i] = cvt_tf32(v[i] - h);
            }
        }
        #pragma unroll
        for (int j = 0; j < 2; j++) {
            int id = tid + 256 * j;
            int r = id >> 5, c = (id & 31) * 4;
            float v[4] = { rb[j].x, rb[j].y, rb[j].z, rb[j].w };
            #pragma unroll
            for (int i = 0; i < 4; i++) {
                float h = cvt_tf32(v[i]);
                Bs_hi[buf][r][c + i] = h;
                if (PREC == 3) Bs_lo[buf][r][c + i] = cvt_tf32(v[i] - h);
            }
        }
        __syncthreads();

        // prefetch next K-slab into regs (overlaps with compute below)
        if (k0 + TBK < K) {
            #pragma unroll
            for (int j = 0; j < 2; j++)
                ra[j] = aV[j] ? *(const float4*)(Az + aOff[j] + k0 + TBK)
                              : make_float4(0.f,0.f,0.f,0.f);
            #pragma unroll
            for (int j = 0; j < 2; j++) {
                int id = tid + 256 * j;
                int r = id >> 5, c4 = id & 31;
                rb[j] = *(const float4*)(B + (long)(k0 + TBK + r) * N + n0 + c4 * 4);
            }
        }

        #pragma unroll
        for (int ks = 0; ks < 2; ks++) {
            int kk = ks * 8;
            unsigned ah[4][4], al[4][4], bh[4][2], bl[4][2];
            #pragma unroll
            for (int mt = 0; mt < 4; mt++) {
                int mr = wm + mt * 16 + g;
                ah[mt][0] = __float_as_uint(As_hi[buf][mr][kk + q]);
                ah[mt][1] = __float_as_uint(As_hi[buf][mr + 8][kk + q]);
                ah[mt][2] = __float_as_uint(As_hi[buf][mr][kk + q + 4]);
                ah[mt][3] = __float_as_uint(As_hi[buf][mr + 8][kk + q + 4]);
                if (PREC == 3) {
                    al[mt][0] = __float_as_uint(As_lo[buf][mr][kk + q]);
                    al[mt][1] = __float_as_uint(As_lo[buf][mr + 8][kk + q]);
                    al[mt][2] = __float_as_uint(As_lo[buf][mr][kk + q + 4]);
                    al[mt][3] = __float_as_uint(As_lo[buf][mr + 8][kk + q + 4]);
                }
            }
            #pragma unroll
            for (int nt = 0; nt < 4; nt++) {
                int nc = wn + nt * 8 + g;
                bh[nt][0] = __float_as_uint(Bs_hi[buf][kk + q][nc]);
                bh[nt][1] = __float_as_uint(Bs_hi[buf][kk + q + 4][nc]);
                if (PREC == 3) {
                    bl[nt][0] = __float_as_uint(Bs_lo[buf][kk + q][nc]);
                    bl[nt][1] = __float_as_uint(Bs_lo[buf][kk + q + 4][nc]);
                }
            }
            #pragma unroll
            for (int mt = 0; mt < 4; mt++)
                #pragma unroll
                for (int nt = 0; nt < 4; nt++) {
                    if (PREC == 3) {
                        mma8(acc[mt][nt], al[mt], bh[nt]);
                        mma8(acc[mt][nt], ah[mt], bl[nt]);
                    }
                    mma8(acc[mt][nt], ah[mt], bh[nt]);
                }
        }
        buf ^= 1;
    }

    // epilogue
    #pragma unroll
    for (int mt = 0; mt < 4; mt++) {
        int r0 = m0 + wm + mt * 16 + g;
        int r1 = r0 + 8;
        #pragma unroll
        for (int nt = 0; nt < 4; nt++) {
            int col = n0 + wn + nt * 8 + 2 * q;
            float b0 = bz[col], b1 = bz[col + 1];
            float v00 = acc[mt][nt][0] + b0, v01 = acc[mt][nt][1] + b1;
            float v10 = acc[mt][nt][2] + b0, v11 = acc[mt][nt][3] + b1;
            if (mode == 1) {
                v00 = gelu_f(v00); v01 = gelu_f(v01);
                v10 = gelu_f(v10); v11 = gelu_f(v11);
            }
            if (mode <= 1) {
                if (r0 < M) { float2 v = make_float2(v00, v01);
                              *(float2*)(Cz + (long)r0 * ldc + col) = v; }
                if (r1 < M) { float2 v = make_float2(v10, v11);
                              *(float2*)(Cz + (long)r1 * ldc + col) = v; }
            } else {
                if (r0 < M) {
                    int tok = idx[r0];
                    float w = outbase[OFF_GATE + (long)tok * NE + z];
                    float* dst = outbase + OFF_STAGE + (long)tok * DM + col;
                    atomicAdd(dst + 0, w * v00);
                    atomicAdd(dst + 1, w * v01);
                }
                if (r1 < M) {
                    int tok = idx[r1];
                    float w = outbase[OFF_GATE + (long)tok * NE + z];
                    float* dst = outbase + OFF_STAGE + (long)tok * DM + col;
                    atomicAdd(dst + 0, w * v10);
                    atomicAdd(dst + 1, w * v11);
                }
            }
        }
    }
}

// ---------------------------------------------------------------------------
// Router logits: g_logits = g_rh1 @ r_w2 + r_b2   (N=8, fp32)
// ---------------------------------------------------------------------------
__global__ void __launch_bounds__(256) logits_kernel(
    const float* __restrict__ r_w2, const float* __restrict__ r_b2)
{
    __shared__ float sh[32 * 257];
    __shared__ float w2s[RHID * NE];
    int tid = threadIdx.x;
    int t0 = blockIdx.x * 32;
    for (int i = tid; i < 32 * RHID; i += 256) {
        int r = i >> 8, c = i & 255;
        sh[r * 257 + c] = g_rh1[(long)(t0 + r) * RHID + c];
    }
    for (int i = tid; i < RHID * NE; i += 256) w2s[i] = r_w2[i];
    __syncthreads();
    int j = tid >> 3, e = tid & 7;
    float acc = r_b2[e];
    #pragma unroll 8
    for (int k = 0; k < RHID; k++) acc += sh[j * 257 + k] * w2s[k * NE + e];
    g_logits[(long)(t0 + j) * NE + e] = acc;
}

// ---------------------------------------------------------------------------
// Gate: exact top-2-with-ties softmax, write gate/scaled/group outputs,
// build per-expert token lists.
// ---------------------------------------------------------------------------
__global__ void __launch_bounds__(256) gate_kernel(float* __restrict__ out)
{
    int t = blockIdx.x * blockDim.x + threadIdx.x;
    if (t >= NTOK) return;
    float l[8];
    #pragma unroll
    for (int e = 0; e < NE; e++) l[e] = g_logits[(long)t * NE + e];

    float m1 = -INFINITY, m2 = -INFINITY;
    #pragma unroll
    for (int e = 0; e < NE; e++) {
        float v = l[e];
        if (v > m1) { m2 = m1; m1 = v; }
        else if (v > m2) { m2 = v; }
    }
    float thresh = m2;

    float w[8];
    float sum = 0.f;
    #pragma unroll
    for (int e = 0; e < NE; e++) {
        if (l[e] >= thresh) { w[e] = expf(l[e] - m1); sum += w[e]; }
        else w[e] = 0.f;
    }
    float rinv = 1.0f / sum;
    #pragma unroll
    for (int e = 0; e < NE; e++) {
        float ww = w[e] * rinv;
        out[OFF_GATE + (long)t * NE + e] = ww;
        out[OFF_SCALED + (long)t * NE + e] = l[e];
        if (l[e] >= thresh) {
            int s = atomicAdd(&g_cnt[e], 1);
            g_idx[e * NTOK + s] = t;
        }
        w[e] = ww;
    }
    #pragma unroll
    for (int g = 0; g < NE / 2; g++)
        out[OFF_GROUP + (long)t * (NE / 2) + g] = w[2 * g] + w[2 * g + 1];
}

// ---------------------------------------------------------------------------
// Final: next_hidden = hidden + alpha * stage_out
// ---------------------------------------------------------------------------
__global__ void __launch_bounds__(256) final_kernel(
    const float* __restrict__ hidden,
    const float* __restrict__ alpha,
    float* __restrict__ out)
{
    long i = ((long)blockIdx.x * 256 + threadIdx.x) * 4;
    float a = *alpha;
    float4 h = *(const float4*)(hidden + i);
    float4 s = *(const float4*)(out + OFF_STAGE + i);
    float4 n;
    n.x = h.x + a * s.x; n.y = h.y + a * s.y;
    n.z = h.z + a * s.z; n.w = h.w + a * s.w;
    *(float4*)(out + OFF_NEXT + i) = n;
}

// ---------------------------------------------------------------------------
extern "C" void kernel_launch(void* const* d_in, const int* in_sizes, int n_in,
                              void* d_out, int out_size)
{
    const float* hidden = (const float*)d_in[0];
    const float* feat   = (const float*)d_in[1];
    const float* bank   = (const float*)d_in[2];   // (tok, 512)
    const float* ln_g  = (const float*)d_in[4];
    const float* ln_b  = (const float*)d_in[5];
    const float* fp_w1 = (const float*)d_in[6];
    const float* fp_b1 = (const float*)d_in[7];
    const float* fp_w2 = (const float*)d_in[8];
    const float* fp_b2 = (const float*)d_in[9];
    const float* r_w1  = (const float*)d_in[10];
    const float* r_b1  = (const float*)d_in[11];
    const float* r_w2  = (const float*)d_in[12];
    const float* r_b2  = (const float*)d_in[13];
    const float* rr_w  = (const float*)d_in[14];
    const float* rr_b  = (const float*)d_in[15];
    const float* e_w1  = (const float*)d_in[16];
    const float* e_b1  = (const float*)d_in[17];
    const float* e_w2  = (const float*)d_in[18];
    const float* e_b2  = (const float*)d_in[19];
    const float* alpha = (const float*)d_in[20];
    float* out = (float*)d_out;

    float *p_hnorm, *p_rin, *p_h1, *p_rh1, *p_Hbuf;
    int *p_cnt, *p_idx;
    cudaGetSymbolAddress((void**)&p_hnorm, g_hnorm);
    cudaGetSymbolAddress((void**)&p_rin,   g_rin);
    cudaGetSymbolAddress((void**)&p_h1,    g_h1);
    cudaGetSymbolAddress((void**)&p_rh1,   g_rh1);
    cudaGetSymbolAddress((void**)&p_Hbuf,  g_Hbuf);
    cudaGetSymbolAddress((void**)&p_cnt,   g_cnt);
    cudaGetSymbolAddress((void**)&p_idx,   g_idx);

    // 1. layernorm (+ rule logits, zero stage_out & counters)
    ln_kernel<<<NTOK, 256>>>(hidden, ln_g, ln_b, feat, rr_w, rr_b, out);

    // 2. feat proj layer 1: gelu(bank @ fp_w1 + b1) -> g_h1   [3xtf32]
    mma_gemm<3><<<dim3(PROJ / TBN, NTOK / TBM, 1), 256>>>(
        bank, fp_w1, fp_b1, p_h1,
        PROJ, RAWF, RAWF, PROJ, 0, 0, 0, 0,
        nullptr, nullptr, NTOK, 1, 0, out);

    // 3. feat proj layer 2: g_h1 @ fp_w2 + b2 -> g_rin[:, 1024:1280]   [3xtf32]
    mma_gemm<3><<<dim3(PROJ / TBN, NTOK / TBM, 1), 256>>>(
        p_h1, fp_w2, fp_b2, p_rin + DM,
        PROJ, PROJ, PROJ, RIN, 0, 0, 0, 0,
        nullptr, nullptr, NTOK, 0, 0, out);

    // 4. router layer 1: gelu(g_rin @ r_w1 + b1) -> g_rh1   [3xtf32]
    mma_gemm<3><<<dim3(RHID / TBN, NTOK / TBM, 1), 256>>>(
        p_rin, r_w1, r_b1, p_rh1,
        RHID, RIN, RIN, RHID, 0, 0, 0, 0,
        nullptr, nullptr, NTOK, 1, 0, out);

    // 5. router layer 2 (N=8) -> g_logits  (fp32)
    logits_kernel<<<NTOK / 32, 256>>>(r_w2, r_b2);

    // 6. gate: top-2 softmax + outputs + expert token lists
    gate_kernel<<<NTOK / 256, 256>>>(out);

    // 7. expert GEMM1 (gathered): gelu(h_norm[idx] @ e_w1[z] + b1[z]) -> g_Hbuf[z]
    //    [single tf32 — post-gating, only stage_out accuracy matters]
    mma_gemm<1><<<dim3(EHID / TBN, NTOK / TBM, NE), 256>>>(
        p_hnorm, e_w1, e_b1, p_Hbuf,
        EHID, DM, DM, EHID,
        0, (long)DM * EHID, (long)NTOK * EHID, EHID,
        p_idx, p_cnt, 0, 1, 1, out);

    // 8. expert GEMM2 + weighted scatter into stage_out   [single tf32]
    mma_gemm<1><<<dim3(DM / TBN, NTOK / TBM, NE), 256>>>(
        p_Hbuf, e_w2, e_b2, out,
        DM, EHID, EHID, DM,
        (long)NTOK * EHID, (long)EHID * DM, 0, DM,
        p_idx, p_cnt, 0, 2, 0, out);

    // 9. next_hidden = hidden + alpha * stage_out
    final_kernel<<<NTOK, 256>>>(hidden, alpha, out);
}